// round 15
// baseline (speedup 1.0000x reference)
#include <cuda_runtime.h>

#define BB 8
#define NN 512
#define PP 32
#define LL 3

typedef unsigned long long ull;

// Scratch (device globals: no allocation in kernel_launch)
__device__ float g_t31[LL][BB*NN*PP];      // [l][b][n][p]
__device__ float g_nu[BB*NN*PP];           // TRANSPOSED: [b][n][p] = (t2[l]@mu_{l-1})[p][n]

// ---- packed f32x2 helpers (sm_100+) ---------------------------------------
__device__ __forceinline__ ull pk(float lo, float hi) {
    ull r; asm("mov.b64 %0,{%1,%2};" : "=l"(r) : "f"(lo), "f"(hi)); return r;
}
__device__ __forceinline__ void upk(ull v, float& lo, float& hi) {
    asm("mov.b64 {%0,%1},%2;" : "=f"(lo), "=f"(hi) : "l"(v));
}
__device__ __forceinline__ ull fma2(ull a, ull b, ull c) {
    ull d; asm("fma.rn.f32x2 %0,%1,%2,%3;" : "=l"(d) : "l"(a), "l"(b), "l"(c));
    return d;
}
__device__ __forceinline__ ull add2(ull a, ull b) {
    ull d; asm("add.rn.f32x2 %0,%1,%2;" : "=l"(d) : "l"(a), "l"(b));
    return d;
}

union F4U2 { float4 f4; ull u2[2]; };

// ---- cp.async helpers ------------------------------------------------------
__device__ __forceinline__ void cp16(float* smem_dst, const float* gsrc) {
    unsigned d = (unsigned)__cvta_generic_to_shared(smem_dst);
    asm volatile("cp.async.ca.shared.global [%0], [%1], 16;"
                 :: "r"(d), "l"(gsrc));
}
__device__ __forceinline__ void cp_commit() {
    asm volatile("cp.async.commit_group;");
}
template <int N>
__device__ __forceinline__ void cp_wait() {
    asm volatile("cp.async.wait_group %0;" :: "n"(N));
}

// ---------------------------------------------------------------------------
// K1 (fused over layers): t31[l][b][n][p] = sum_m relu(A + B*w + C*s)
//   = 0.5*(Sum v + Sum|v|);  Sum v closed-form via row sums.
// grid (N, B), block 256. lane = p; 8 warps split m; 3 layers interleaved.
// ---------------------------------------------------------------------------
__global__ __launch_bounds__(256) void edge_kernel(
    const float* __restrict__ x, const float* __restrict__ wgt,
    const float* __restrict__ t4)
{
    __shared__ float w_s[NN];
    __shared__ float s_s[NN];
    __shared__ float red_s[LL][8][PP];
    __shared__ float rw_s[8], rs_s[8];

    int n = blockIdx.x, b = blockIdx.y;
    int tid = threadIdx.x;
    int lane = tid & 31;
    int wid  = tid >> 5;

    const float* wrow = wgt + ((size_t)(b * NN + n)) * NN;
    const float* xb   = x + b * NN;

    float pw = 0.f, ps = 0.f;
    for (int m = tid; m < NN; m += 256) {
        float w = wrow[m];
        float s = 2.0f * xb[m] - 1.0f;
        w_s[m] = w;
        s_s[m] = s;
        pw += w;
        ps += s;
    }
    #pragma unroll
    for (int o = 16; o; o >>= 1) {
        pw += __shfl_xor_sync(0xffffffffu, pw, o);
        ps += __shfl_xor_sync(0xffffffffu, ps, o);
    }
    if (lane == 0) { rw_s[wid] = pw; rs_s[wid] = ps; }

    float xn = xb[n];
    float sn = 2.0f * xn - 1.0f;

    float As[LL], Bs[LL], Cs[LL];
    ull A2[LL], B2[LL], C2[LL];
    #pragma unroll
    for (int l = 0; l < LL; l++) {
        const float* t4p = t4 + (l * PP + lane) * 4;
        float c0 = t4p[0], c1 = t4p[1], c2 = t4p[2], c3 = t4p[3];
        float A  = fmaf(c0, xn, fmaf(0.5f, c2, c3));
        float C  = -0.5f * c2 * sn;
        As[l] = A; Bs[l] = c1; Cs[l] = C;
        A2[l] = pk(A, A);
        B2[l] = pk(c1, c1);
        C2[l] = pk(C, C);
    }

    __syncthreads();

    float sw = 0.f, ss = 0.f;
    #pragma unroll
    for (int k = 0; k < 8; k++) { sw += rw_s[k]; ss += rs_s[k]; }

    const ull ABSM = 0x7fffffff7fffffffULL;
    ull sa[LL] = {0, 0, 0};   // packed sum of |v|

    int m0 = wid * (NN / 8);
    #pragma unroll 4
    for (int m = m0; m < m0 + NN / 8; m += 4) {
        F4U2 w4, s4;
        w4.f4 = *(const float4*)(w_s + m);
        s4.f4 = *(const float4*)(s_s + m);
        #pragma unroll
        for (int l = 0; l < LL; l++) {
            ull v0 = fma2(C2[l], s4.u2[0], fma2(B2[l], w4.u2[0], A2[l]));
            ull v1 = fma2(C2[l], s4.u2[1], fma2(B2[l], w4.u2[1], A2[l]));
            sa[l] = add2(sa[l], add2(v0 & ABSM, v1 & ABSM));
        }
    }

    #pragma unroll
    for (int l = 0; l < LL; l++) {
        float a, bb;
        upk(sa[l], a, bb);
        red_s[l][wid][lane] = a + bb;
    }
    __syncthreads();

    if (wid < LL) {
        int l = wid;
        float stot = red_s[l][0][lane];
        #pragma unroll
        for (int k = 1; k < 8; k++) stot += red_s[l][k][lane];
        float sv = fmaf(512.0f, As[l], fmaf(Bs[l], sw, Cs[l] * ss));
        g_t31[l][(b * NN + n) * PP + lane] = 0.5f * (sv + stot);
    }
}

// ---------------------------------------------------------------------------
// K2 (per layer): z + epilogue + next-layer nu. One block per (16-j tile, b).
//   grid (32, 8) = 256 blocks, 256 threads, ~111KB smem -> 2 blocks/SM.
//   Mainloop: warp g owns n in [64g, 64g+64); thread = 4p x 4j (16 acc);
//   per n: LDS.128 adj (4j) + LDS.128 nu (4p, broadcast) + 16 FFMA.
//   8-way n-reduction via smem (conflict-free), then inline epilogue.
// ---------------------------------------------------------------------------
#define JT      16                     // j per tile
#define SM_A    0                      // a_s  [512][16]  (reused as red[4096])
#define SM_NUS  (NN*JT)                // nu_s [512][32]
#define SM_T31  (SM_NUS + NN*32)       // t31_s [16][33]
#define SM_T3   (SM_T31 + JT*33)       // t3t_s [32][33]
#define SM_T2N  (SM_T3 + 32*33)        // t2n_s [32][33]
#define SM_MU   (SM_T2N + 32*33)       // mu_s  [16][33]
#define SM_TOT  (SM_MU + JT*33)        // floats (~111KB)

__global__ void __launch_bounds__(256, 2) layer_kernel(
    const float* __restrict__ x, const float* __restrict__ extra,
    const float* __restrict__ adj,
    const float* __restrict__ t1, const float* __restrict__ t2,
    const float* __restrict__ t3, int layer, int has_z,
    float* __restrict__ out)
{
    extern __shared__ float sm[];
    float* a_s   = sm + SM_A;
    float* nu_s  = sm + SM_NUS;
    float* t31_s = sm + SM_T31;
    float* t3t_s = sm + SM_T3;
    float* t2n_s = sm + SM_T2N;
    float* mu_s  = sm + SM_MU;

    int jt = blockIdx.x, b = blockIdx.y;
    int tid  = threadIdx.x;
    int lane = tid & 31;
    int g    = tid >> 5;               // warp 0..7 -> n in [64g, 64g+64)
    int j0   = jt * JT;
    int pgq  = lane >> 2;              // 0..7: p group (4 p each)
    int jq   = lane & 3;               // 0..3: j group (4 j each)

    if (has_z) {
        // stage adj strip [512][16]: 2048 cp16
        #pragma unroll
        for (int pass = 0; pass < 8; pass++) {
            int i = tid + pass * 256;
            int row = i >> 2, seg = (i & 3) * 4;
            cp16(&a_s[row * JT + seg],
                 adj + ((size_t)(b * NN + row)) * NN + j0 + seg);
        }
        // stage nu strip [512][32]: 4096 cp16
        #pragma unroll
        for (int pass = 0; pass < 16; pass++) {
            int i = tid + pass * 256;
            int row = i >> 3, seg = (i & 7) * 4;
            cp16(&nu_s[row * 32 + seg],
                 g_nu + ((size_t)(b * NN + row)) * 32 + seg);
        }
        cp_commit();
    }

    // stage epilogue tiles (plain loads; overlap with cp.async)
    #pragma unroll
    for (int pass = 0; pass < 2; pass++) {
        int idx = tid + pass * 256;               // jl*32 + q (512 total)
        int jl = idx >> 5, q = idx & 31;
        t31_s[jl * 33 + q] = g_t31[layer][((size_t)b * NN + j0 + jl) * PP + q];
    }
    #pragma unroll
    for (int pass = 0; pass < 4; pass++) {
        int idx = tid + pass * 256;               // p*32 + q
        int p = idx >> 5, q = idx & 31;
        t3t_s[q * 33 + p] = t3[layer * PP * PP + idx];
        if (layer < 2)
            t2n_s[q * 33 + p] = t2[(layer + 1) * PP * PP + idx];
    }

    if (has_z) cp_wait<0>();
    __syncthreads();

    float acc[4][4];
    #pragma unroll
    for (int i = 0; i < 4; i++)
        #pragma unroll
        for (int jj = 0; jj < 4; jj++) acc[i][jj] = 0.f;

    if (has_z) {
        int nbase = g * 64;
        #pragma unroll 4
        for (int nn = 0; nn < 64; nn++) {
            int n = nbase + nn;
            float4 a4 = *(const float4*)&a_s[n * JT + jq * 4];
            float4 p4 = *(const float4*)&nu_s[n * 32 + pgq * 4];
            const float pv[4] = {p4.x, p4.y, p4.z, p4.w};
            const float av[4] = {a4.x, a4.y, a4.z, a4.w};
            #pragma unroll
            for (int i = 0; i < 4; i++)
                #pragma unroll
                for (int jj = 0; jj < 4; jj++)
                    acc[i][jj] = fmaf(pv[i], av[jj], acc[i][jj]);
        }

        // 8-way n-reduction via smem (reuse a_s region; conflict-free)
        __syncthreads();
        #pragma unroll
        for (int i = 0; i < 4; i++)
            #pragma unroll
            for (int jj = 0; jj < 4; jj++)
                a_s[(i * 4 + jj) * 256 + g * 32 + lane] = acc[i][jj];
        __syncthreads();
    }

    // epilogue: thread handles 2 outputs: i4 = 2*c, 2*c+1 (c = warp), l = lane
    // p = (l>>2)*4 + (i4>>2);  jl = (l&3)*4 + (i4&3) and jl+1
    int c = g, l = lane;
    int i40 = 2 * c;
    int p   = (l >> 2) * 4 + (i40 >> 2);
    int jl0 = (l & 3) * 4 + (i40 & 3);
    int jl1 = jl0 + 1;

    float zs0 = 0.f, zs1 = 0.f;
    if (has_z) {
        #pragma unroll
        for (int gg = 0; gg < 8; gg++) {
            zs0 += a_s[i40 * 256 + gg * 32 + l];
            zs1 += a_s[(i40 + 1) * 256 + gg * 32 + l];
        }
    }

    int jg0 = j0 + jl0;
    float xv0 = x[b * NN + jg0],     xv1 = x[b * NN + jg0 + 1];
    float ev0 = extra[b * NN + jg0], ev1 = extra[b * NN + jg0 + 1];

    const float* t1p = t1 + (layer * PP + p) * 3;
    float c0 = t1p[0], c1 = t1p[1], c2 = t1p[2];
    float mu0 = zs0 + fmaf(c0, 1.0f - xv0, fmaf(c2, ev0, c1));
    float mu1 = zs1 + fmaf(c0, 1.0f - xv1, fmaf(c2, ev1, c1));

    #pragma unroll
    for (int q = 0; q < PP; q++) {
        float t3v = t3t_s[q * 33 + p];
        mu0 = fmaf(t3v, t31_s[jl0 * 33 + q], mu0);
        mu1 = fmaf(t3v, t31_s[jl1 * 33 + q], mu1);
    }
    mu0 = fmaxf(mu0, 0.0f);
    mu1 = fmaxf(mu1, 0.0f);

    if (layer == 2) {
        out[((size_t)b * PP + p) * NN + jg0]     = mu0;
        out[((size_t)b * PP + p) * NN + jg0 + 1] = mu1;
        return;
    }

    mu_s[jl0 * 33 + p] = mu0;
    mu_s[jl1 * 33 + p] = mu1;
    __syncthreads();

    float nu0 = 0.f, nu1 = 0.f;
    #pragma unroll
    for (int q = 0; q < PP; q++) {
        float t2v = t2n_s[q * 33 + p];
        nu0 = fmaf(t2v, mu_s[jl0 * 33 + q], nu0);
        nu1 = fmaf(t2v, mu_s[jl1 * 33 + q], nu1);
    }

    g_nu[((size_t)b * NN + jg0) * 32 + p]     = nu0;
    g_nu[((size_t)b * NN + jg0 + 1) * 32 + p] = nu1;
}

// ---------------------------------------------------------------------------
extern "C" void kernel_launch(void* const* d_in, const int* in_sizes, int n_in,
                              void* d_out, int out_size)
{
    const float* x     = (const float*)d_in[0];
    const float* adj   = (const float*)d_in[1];
    const float* wgt   = (const float*)d_in[2];
    const float* extra = (const float*)d_in[3];
    const float* t1    = (const float*)d_in[4];
    const float* t2    = (const float*)d_in[5];
    const float* t3    = (const float*)d_in[6];
    const float* t4    = (const float*)d_in[7];
    float* out = (float*)d_out;

    static const size_t smem_bytes = SM_TOT * sizeof(float);
    cudaFuncSetAttribute(layer_kernel,
                         cudaFuncAttributeMaxDynamicSharedMemorySize,
                         (int)smem_bytes);

    dim3 edge_grid(NN, BB);
    dim3 lay_grid(NN / JT, BB);   // (32, 8)

    edge_kernel<<<edge_grid, 256>>>(x, wgt, t4);

    // layer 0: no z; writes g_nu = t2[1] @ mu0 (transposed)
    layer_kernel<<<lay_grid, 256, smem_bytes>>>(x, extra, adj, t1, t2, t3, 0, 0, out);
    // layer 1: z = nu@adj; writes g_nu = t2[2] @ mu1
    layer_kernel<<<lay_grid, 256, smem_bytes>>>(x, extra, adj, t1, t2, t3, 1, 1, out);
    // layer 2: z = nu@adj; writes mu2 -> out
    layer_kernel<<<lay_grid, 256, smem_bytes>>>(x, extra, adj, t1, t2, t3, 2, 1, out);
}